// round 17
// baseline (speedup 1.0000x reference)
#include <cuda_runtime.h>
#include <cstdint>
#include <cstddef>

#define BB 64      // batch
#define TT 512     // time
#define HH 256     // hidden
#define GG 1024    // 4*H
#define NBGRP 4    // batch groups of 16
#define BAR_PER 16 // CTAs per (layer,bgrp) barrier group (16 hgrps)
#define WSTR 1028  // W smem hid stride (floats): 4112B mod 128B = 16 -> staggered phases

// ---------------- device scratch (static, no allocations) ----------------
__device__ float g_xg[(size_t)TT * BB * GG];   // layer-0 gate pre-activations [t*64+b][4H]
__device__ float g_ys[(size_t)TT * BB * HH];   // y0 stream [t][b][h] (layer-1 input)
__device__ float g_h0buf[2][BB * HH];          // layer-0 h ping-pong, [b][hid]
__device__ float g_h1buf[2][BB * HH];          // layer-1 h ping-pong, [b][hid]
__device__ float g_masks[6 * BB * HH];         // (layer,{out,h,c}) masks [B][H]
__device__ unsigned g_bar[8 * 32];             // [layer*4+bgrp]*32 monotone counters, 128B apart

// ---------------- f32x2 packed math helpers ----------------
__device__ __forceinline__ uint64_t pack2(float lo, float hi) {
    uint64_t r; asm("mov.b64 %0, {%1,%2};" : "=l"(r) : "f"(lo), "f"(hi)); return r;
}
__device__ __forceinline__ void unpack2(uint64_t v, float& lo, float& hi) {
    asm("mov.b64 {%0,%1}, %2;" : "=f"(lo), "=f"(hi) : "l"(v));
}
#define FFMA2(acc, a, b) asm("fma.rn.f32x2 %0, %1, %2, %0;" : "+l"(acc) : "l"(a), "l"(b))

// ---------------- barrier primitives (release/acquire, gpu scope) ----------------
__device__ __forceinline__ void red_add_release(unsigned* p, unsigned v) {
    asm volatile("red.release.gpu.global.add.u32 [%0], %1;" :: "l"(p), "r"(v) : "memory");
}
__device__ __forceinline__ unsigned ld_acquire(const unsigned* p) {
    unsigned v; asm volatile("ld.acquire.gpu.global.u32 %0, [%1];" : "=r"(v) : "l"(p) : "memory");
    return v;
}

// ---------------- Threefry-2x32 (JAX, partitionable) — VALIDATED bit-exact ----------------
__device__ __forceinline__ uint32_t rotl32(uint32_t x, int n) { return __funnelshift_l(x, x, n); }

__device__ __forceinline__ void tf2x32(uint32_t k0, uint32_t k1, uint32_t x0, uint32_t x1,
                                       uint32_t& o0, uint32_t& o1) {
    uint32_t ks2 = k0 ^ k1 ^ 0x1BD11BDAu;
    x0 += k0; x1 += k1;
#define TFR(r) { x0 += x1; x1 = rotl32(x1, (r)); x1 ^= x0; }
    TFR(13) TFR(15) TFR(26) TFR(6)   x0 += k1;  x1 += ks2 + 1u;
    TFR(17) TFR(29) TFR(16) TFR(24)  x0 += ks2; x1 += k0 + 2u;
    TFR(13) TFR(15) TFR(26) TFR(6)   x0 += k0;  x1 += k1 + 3u;
    TFR(17) TFR(29) TFR(16) TFR(24)  x0 += k1;  x1 += ks2 + 4u;
    TFR(13) TFR(15) TFR(26) TFR(6)   x0 += ks2; x1 += k0 + 5u;
#undef TFR
    o0 = x0; o1 = x1;
}

__global__ void compute_masks_kernel() {
    int idx = blockIdx.x * 256 + threadIdx.x;
    if (idx >= 6 * BB * HH) return;
    int l = idx / (3 * BB * HH);
    int j = (idx / (BB * HH)) % 3;
    uint32_t e = (uint32_t)(idx % (BB * HH));
    uint32_t a0, a1, b0, b1, c0, c1;
    tf2x32(0u, 42u, 0u, (uint32_t)l, a0, a1);
    tf2x32(a0, a1, 0u, (uint32_t)j, b0, b1);
    tf2x32(b0, b1, 0u, e, c0, c1);
    uint32_t bits = c0 ^ c1;
    float u = __uint_as_float((bits >> 9) | 0x3f800000u) - 1.0f;
    g_masks[idx] = (u < 0.75f) ? (1.0f / 0.75f) : 0.0f;
}

__global__ void zero_state_kernel() {
    int i = blockIdx.x * 256 + threadIdx.x;
    if (i < BB * HH) {
        g_h0buf[0][i] = 0.0f;
        g_h0buf[1][i] = 0.0f;
        g_h1buf[0][i] = 0.0f;
        g_h1buf[1][i] = 0.0f;
    }
    if (i < 8 * 32) g_bar[i] = 0u;   // reset per replay (determinism)
}

// ---------------- layer-0 big GEMM (f32x2, double-buffered, LDS.128 A-feed) ----------------
__global__ void __launch_bounds__(256) gemm_xg_kernel(const float* __restrict__ A,
                                                      const float* __restrict__ W,
                                                      const float* __restrict__ bih,
                                                      const float* __restrict__ bhh) {
    __shared__ uint64_t As2[16][132];   // (a,a) dup pairs, [k][m]
    __shared__ float Bs[16][68];        // [k][n]
    const int tid = threadIdx.x;
    const int arow_l = tid >> 1;
    const int ak = (tid & 1) << 3;
    const int m = blockIdx.x * 128 + arow_l;
    const float* Arow = A + ((size_t)(m & 63) * TT + (size_t)(m >> 6)) * HH;
    const int brow_l = tid >> 2;
    const int bk = (tid & 3) << 2;
    const float* Wrow = W + (size_t)(blockIdx.y * 64 + brow_l) * HH;
    const int tx = tid & 15, ty = tid >> 4;

    uint64_t acc[8][2];
#pragma unroll
    for (int i = 0; i < 8; i++) { acc[i][0] = 0ull; acc[i][1] = 0ull; }

    float4 a0v = *reinterpret_cast<const float4*>(Arow + ak);
    float4 a1v = *reinterpret_cast<const float4*>(Arow + ak + 4);
    float4 bv  = *reinterpret_cast<const float4*>(Wrow + bk);

    for (int k0 = 0; k0 < 256; k0 += 16) {
        As2[ak + 0][arow_l] = pack2(a0v.x, a0v.x);
        As2[ak + 1][arow_l] = pack2(a0v.y, a0v.y);
        As2[ak + 2][arow_l] = pack2(a0v.z, a0v.z);
        As2[ak + 3][arow_l] = pack2(a0v.w, a0v.w);
        As2[ak + 4][arow_l] = pack2(a1v.x, a1v.x);
        As2[ak + 5][arow_l] = pack2(a1v.y, a1v.y);
        As2[ak + 6][arow_l] = pack2(a1v.z, a1v.z);
        As2[ak + 7][arow_l] = pack2(a1v.w, a1v.w);
        Bs[bk + 0][brow_l] = bv.x;
        Bs[bk + 1][brow_l] = bv.y;
        Bs[bk + 2][brow_l] = bv.z;
        Bs[bk + 3][brow_l] = bv.w;
        __syncthreads();
        if (k0 + 16 < 256) {
            a0v = *reinterpret_cast<const float4*>(Arow + k0 + 16 + ak);
            a1v = *reinterpret_cast<const float4*>(Arow + k0 + 16 + ak + 4);
            bv  = *reinterpret_cast<const float4*>(Wrow + k0 + 16 + bk);
        }
#pragma unroll
        for (int kk = 0; kk < 16; kk++) {
            ulonglong2 w2 = *reinterpret_cast<const ulonglong2*>(&Bs[kk][tx << 2]);
            const ulonglong2* ap = reinterpret_cast<const ulonglong2*>(&As2[kk][ty << 3]);
            ulonglong2 a01 = ap[0];
            ulonglong2 a23 = ap[1];
            ulonglong2 a45 = ap[2];
            ulonglong2 a67 = ap[3];
            FFMA2(acc[0][0], w2.x, a01.x); FFMA2(acc[0][1], w2.y, a01.x);
            FFMA2(acc[1][0], w2.x, a01.y); FFMA2(acc[1][1], w2.y, a01.y);
            FFMA2(acc[2][0], w2.x, a23.x); FFMA2(acc[2][1], w2.y, a23.x);
            FFMA2(acc[3][0], w2.x, a23.y); FFMA2(acc[3][1], w2.y, a23.y);
            FFMA2(acc[4][0], w2.x, a45.x); FFMA2(acc[4][1], w2.y, a45.x);
            FFMA2(acc[5][0], w2.x, a45.y); FFMA2(acc[5][1], w2.y, a45.y);
            FFMA2(acc[6][0], w2.x, a67.x); FFMA2(acc[6][1], w2.y, a67.x);
            FFMA2(acc[7][0], w2.x, a67.y); FFMA2(acc[7][1], w2.y, a67.y);
        }
        __syncthreads();
    }
    const int n0 = blockIdx.y * 64 + (tx << 2);
    const float bv0 = bih[n0 + 0] + bhh[n0 + 0];
    const float bv1 = bih[n0 + 1] + bhh[n0 + 1];
    const float bv2 = bih[n0 + 2] + bhh[n0 + 2];
    const float bv3 = bih[n0 + 3] + bhh[n0 + 3];
#pragma unroll
    for (int i = 0; i < 8; i++) {
        int m2 = blockIdx.x * 128 + (ty << 3) + i;
        float a0, a1, a2, a3;
        unpack2(acc[i][0], a0, a1);
        unpack2(acc[i][1], a2, a3);
        *reinterpret_cast<float4*>(&g_xg[(size_t)m2 * GG + n0]) =
            make_float4(a0 + bv0, a1 + bv1, a2 + bv2, a3 + bv3);
    }
}

// ---------------- shared inner matvec: acc += W[gate][k] * src[k] over 256 k ----------------
__device__ __forceinline__ void matvec_acc(const float* __restrict__ wbase,
                                           const float* __restrict__ srow,
                                           uint64_t& a_i, uint64_t& a_f,
                                           uint64_t& a_c, uint64_t& a_o) {
#pragma unroll 8
    for (int k = 0; k < 256; k += 4) {
        ulonglong2 h01 = *reinterpret_cast<const ulonglong2*>(srow + k);
        ulonglong2 wi = *reinterpret_cast<const ulonglong2*>(wbase + k);
        ulonglong2 wf = *reinterpret_cast<const ulonglong2*>(wbase + 256 + k);
        ulonglong2 wc = *reinterpret_cast<const ulonglong2*>(wbase + 512 + k);
        ulonglong2 wo = *reinterpret_cast<const ulonglong2*>(wbase + 768 + k);
        FFMA2(a_i, wi.x, h01.x); FFMA2(a_i, wi.y, h01.y);
        FFMA2(a_f, wf.x, h01.x); FFMA2(a_f, wf.y, h01.y);
        FFMA2(a_c, wc.x, h01.x); FFMA2(a_c, wc.y, h01.y);
        FFMA2(a_o, wo.x, h01.x); FFMA2(a_o, wo.y, h01.y);
    }
}

// stage a [16 hid][gate-major 1024] W matrix slice into smem (256 threads)
__device__ __forceinline__ void stage_W(float* __restrict__ dst, const float* __restrict__ W,
                                        int hid0, int tid) {
#pragma unroll
    for (int j = 0; j < 16; j++) {
        int f = tid + (j << 8);              // float4 index 0..4095
        int hidp = f >> 8, gate = (f >> 6) & 3, k4 = f & 63;
        float4 v = __ldg(reinterpret_cast<const float4*>(
            W + ((size_t)(gate << 8) + (size_t)(hid0 + hidp)) * HH) + k4);
        *reinterpret_cast<float4*>(dst + hidp * WSTR + gate * 256 + (k4 << 2)) = v;
    }
}

// stage a [16 b][256] float slice (contiguous rows of 256) into padded smem rows of 260
__device__ __forceinline__ void stage_slice(float* __restrict__ dst,
                                            const float* __restrict__ src, int tid) {
#pragma unroll
    for (int j = 0; j < 4; j++) {
        int idx = tid + (j << 8);          // 0..1023 float4s
        float4 v = __ldcg(reinterpret_cast<const float4*>(src) + idx);
        int r = idx >> 6, k4 = idx & 63;
        *reinterpret_cast<float4*>(dst + r * 260 + (k4 << 2)) = v;
    }
}

// ---------------- fused pipelined two-layer recurrence ----------------
// 128 CTAs x 256 threads (1/SM). CTAs 0..63: layer 0 (16 hid x 16 b).
// CTAs 64..127: layer 1 (16 hid x 16 b), xg computed on the fly from y0 stream.
// Layer 0 has no backpressure; layer 1 trails it by >=1 step via bar0 flags.
__global__ void __launch_bounds__(256, 1) fused_lstm_kernel(
    const float* __restrict__ Whh0, const float* __restrict__ Whh1,
    const float* __restrict__ Wih1, const float* __restrict__ bih1,
    const float* __restrict__ bhh1, float* __restrict__ yout) {
    extern __shared__ float sm[];
    float* W4a = sm;                         // [16 hid][WSTR] W_hh (own layer)
    float* W4b = sm + 16 * WSTR;             // [16 hid][WSTR] W_ih1 (layer 1 only)
    float* hs  = sm + 32 * WSTR;             // [16 b][260] h slice
    float* ys  = hs + 16 * 260;              // [16 b][260] y0 slice (layer 1 only)

    const int tid = threadIdx.x;
    const int lane = tid & 31;
    const int wid = tid >> 5;
    const int hid_l = (wid << 1) + (lane >> 4);   // 0..15
    const int b_l = lane & 15;                    // 0..15
    const int layer = (blockIdx.x >= 64) ? 1 : 0;
    const int lb = blockIdx.x & 63;
    const int hgrp = lb >> 2;            // 0..15 (16 hids each)
    const int bgrp = lb & 3;             // 0..3  (16 b each)
    const int hid = hgrp * 16 + hid_l;
    const int b = bgrp * 16 + b_l;
    unsigned* bar0p = &g_bar[bgrp * 32];
    unsigned* bar1p = &g_bar[(4 + bgrp) * 32];

    const int mi = b * HH + hid;
    const float mo  = g_masks[(layer * 3 + 0) * BB * HH + mi];
    const float mh  = g_masks[(layer * 3 + 1) * BB * HH + mi];
    const float mcm = g_masks[(layer * 3 + 2) * BB * HH + mi];
    float c = 0.0f;
    const float* wbase = W4a + hid_l * WSTR;
    const float* hrow = hs + b_l * 260;

    if (layer == 0) {
        // ================= LAYER 0 =================
        stage_W(W4a, Whh0, hgrp * 16, tid);
        float xi, xf, xc, xo;
        {
            size_t xb = (size_t)b * GG + hid;
            xi = __ldcs(&g_xg[xb]);
            xf = __ldcs(&g_xg[xb + 256]);
            xc = __ldcs(&g_xg[xb + 512]);
            xo = __ldcs(&g_xg[xb + 768]);
        }
        __syncthreads();

        for (int t = 0; t < TT; t++) {
            const int cur = t & 1;
            stage_slice(hs, g_h0buf[cur] + (size_t)bgrp * 16 * HH, tid);
            __syncthreads();

            uint64_t a_i = pack2(xi, 0.0f), a_f = pack2(xf, 0.0f);
            uint64_t a_c = pack2(xc, 0.0f), a_o = pack2(xo, 0.0f);
            matvec_acc(wbase, hrow, a_i, a_f, a_c, a_o);
            float gi, gf, gc, go, tmp;
            unpack2(a_i, gi, tmp); gi += tmp;
            unpack2(a_f, gf, tmp); gf += tmp;
            unpack2(a_c, gc, tmp); gc += tmp;
            unpack2(a_o, go, tmp); go += tmp;

            if (t + 1 < TT) {   // prefetch next xg under the sync
                size_t xb = ((size_t)(t + 1) * BB + b) * GG + hid;
                xi = __ldcs(&g_xg[xb]);
                xf = __ldcs(&g_xg[xb + 256]);
                xc = __ldcs(&g_xg[xb + 512]);
                xo = __ldcs(&g_xg[xb + 768]);
            }

            float i_ = __fdividef(1.0f, 1.0f + __expf(-gi));
            float f_ = __fdividef(1.0f, 1.0f + __expf(-gf));
            float o_ = __fdividef(1.0f, 1.0f + __expf(-go));
            float tg = 1.0f - __fdividef(2.0f, __expf(2.0f * gc) + 1.0f);
            float cn = f_ * c + i_ * tg;
            float th = 1.0f - __fdividef(2.0f, __expf(2.0f * cn) + 1.0f);
            float hn = o_ * th;
            c = cn * mcm;

            __stcg(&g_h0buf[cur ^ 1][mi], hn * mh);                    // next-h (peers wait)
            __stcg(&g_ys[((size_t)t * BB + b) * HH + hid], hn * mo);   // y0 stream (layer 1)

            __syncthreads();    // all stores precede the release-arrive
            if (tid == 0) {
                red_add_release(bar0p, 1u);
                if (t + 1 < TT) {
                    unsigned tgt = (unsigned)(t + 1) * BAR_PER;
                    while (ld_acquire(bar0p) < tgt) { }
                }
            }
            __syncthreads();
        }
    } else {
        // ================= LAYER 1 =================
        stage_W(W4a, Whh1, hgrp * 16, tid);
        stage_W(W4b, Wih1, hgrp * 16, tid);
        const float* wbase_i = W4b + hid_l * WSTR;
        const float* yrow_s = ys + b_l * 260;
        const float bi = bih1[hid]       + bhh1[hid];
        const float bf = bih1[256 + hid] + bhh1[256 + hid];
        const float bc = bih1[512 + hid] + bhh1[512 + hid];
        const float bo = bih1[768 + hid] + bhh1[768 + hid];
        float* yrow = yout + (size_t)b * (TT * HH) + hid;
        __syncthreads();

        for (int t = 0; t < TT; t++) {
            const int cur = t & 1;
            // wait for y0(t) from layer 0 (usually already far ahead)
            if (tid == 0) {
                unsigned tgt = (unsigned)(t + 1) * BAR_PER;
                while (ld_acquire(bar0p) < tgt) { }
            }
            __syncthreads();

            stage_slice(ys, g_ys + ((size_t)t * BB + (size_t)bgrp * 16) * HH, tid);
            stage_slice(hs, g_h1buf[cur] + (size_t)bgrp * 16 * HH, tid);
            __syncthreads();

            uint64_t a_i = pack2(bi, 0.0f), a_f = pack2(bf, 0.0f);
            uint64_t a_c = pack2(bc, 0.0f), a_o = pack2(bo, 0.0f);
            matvec_acc(wbase_i, yrow_s, a_i, a_f, a_c, a_o);   // W_ih1 @ y0(t)
            matvec_acc(wbase,   hrow,   a_i, a_f, a_c, a_o);   // W_hh1 @ h1(t)
            float gi, gf, gc, go, tmp;
            unpack2(a_i, gi, tmp); gi += tmp;
            unpack2(a_f, gf, tmp); gf += tmp;
            unpack2(a_c, gc, tmp); gc += tmp;
            unpack2(a_o, go, tmp); go += tmp;

            float i_ = __fdividef(1.0f, 1.0f + __expf(-gi));
            float f_ = __fdividef(1.0f, 1.0f + __expf(-gf));
            float o_ = __fdividef(1.0f, 1.0f + __expf(-go));
            float tg = 1.0f - __fdividef(2.0f, __expf(2.0f * gc) + 1.0f);
            float cn = f_ * c + i_ * tg;
            float th = 1.0f - __fdividef(2.0f, __expf(2.0f * cn) + 1.0f);
            float hn = o_ * th;
            c = cn * mcm;

            __stcg(&g_h1buf[cur ^ 1][mi], hn * mh);   // critical path first
            yrow[(size_t)t * HH] = hn * mo;           // final output

            if (t + 1 < TT) {
                __syncthreads();
                if (tid == 0) {
                    red_add_release(bar1p, 1u);
                    unsigned tgt = (unsigned)(t + 1) * BAR_PER;
                    while (ld_acquire(bar1p) < tgt) { }
                }
                __syncthreads();
            }
        }
    }
}

// ---------------- launch (4 graph nodes) ----------------
extern "C" void kernel_launch(void* const* d_in, const int* in_sizes, int n_in,
                              void* d_out, int out_size) {
    const float* x    = (const float*)d_in[0];
    const float* Wih0 = (const float*)d_in[1];
    const float* Whh0 = (const float*)d_in[2];
    const float* bih0 = (const float*)d_in[3];
    const float* bhh0 = (const float*)d_in[4];
    const float* Wih1 = (const float*)d_in[5];
    const float* Whh1 = (const float*)d_in[6];
    const float* bih1 = (const float*)d_in[7];
    const float* bhh1 = (const float*)d_in[8];
    float* out = (float*)d_out;

    const int smem = (32 * WSTR + 2 * 16 * 260) * 4;   // (32896 + 8320)*4 = 164864 B
    cudaFuncSetAttribute(fused_lstm_kernel, cudaFuncAttributeMaxDynamicSharedMemorySize, smem);

    compute_masks_kernel<<<(6 * BB * HH + 255) / 256, 256>>>();
    zero_state_kernel<<<(BB * HH + 255) / 256, 256>>>();
    gemm_xg_kernel<<<dim3((TT * BB) / 128, GG / 64), 256>>>(x, Wih0, bih0, bhh0);
    fused_lstm_kernel<<<128, 256, smem>>>(Whh0, Whh1, Wih1, bih1, bhh1, out);
}